// round 12
// baseline (speedup 1.0000x reference)
#include <cuda_runtime.h>
#include <cuda_fp16.h>
#include <math.h>
#include <cstdint>

#define NN   50000
#define EE   800000
#define ET   (NN + EE)     // 850000 edges incl. self loops
#define DHID 128
#define DOUT 64

// ---------------- device scratch (static, no allocation) ----------------
__device__ __align__(16) unsigned long long g_hist[NN];  // cnt<<32 | sumw*2^24
__device__ __align__(16) int   g_rowptr[NN + 1];
__device__ __align__(16) int   g_cursor[NN];
__device__ __align__(16) int   g_vctr[4];           // work-queue cursors
__device__ __align__(16) int2  g_edge[ET];          // (src*64, w bits)
__device__ __align__(16) __half g_xlh[NN * DHID];   // xl in fp16
__device__ __align__(16) float  g_xr[NN * DHID];
__device__ __align__(16) float  g_h [NN * DHID];
// pre-transposed fp16 weight images, row-major N x K (K=128)
__device__ __align__(16) __half g_wimg[4 * 16384 + 2 * 8192];

// ---------------- helpers ----------------
__device__ __forceinline__ uint32_t smem_to_u32(const void* p) {
    uint32_t a;
    asm("{ .reg .u64 t; cvta.to.shared.u64 t, %1; cvt.u32.u64 %0, t; }"
        : "=r"(a) : "l"(p));
    return a;
}
__device__ __forceinline__ void ldsm4(uint32_t* r, uint32_t addr) {
    asm volatile("ldmatrix.sync.aligned.m8n8.x4.shared.b16 {%0,%1,%2,%3}, [%4];"
        : "=r"(r[0]), "=r"(r[1]), "=r"(r[2]), "=r"(r[3]) : "r"(addr));
}
__device__ __forceinline__ void mma16816(float* d, const uint32_t* a,
                                         uint32_t b0, uint32_t b1) {
    asm volatile("mma.sync.aligned.m16n8k16.row.col.f32.f16.f16.f32 "
        "{%0,%1,%2,%3}, {%4,%5,%6,%7}, {%8,%9}, {%0,%1,%2,%3};"
        : "+f"(d[0]), "+f"(d[1]), "+f"(d[2]), "+f"(d[3])
        : "r"(a[0]), "r"(a[1]), "r"(a[2]), "r"(a[3]), "r"(b0), "r"(b1));
}

// ---------------- CSR build ----------------
__global__ void k_zero() {
    int i = blockIdx.x * blockDim.x + threadIdx.x;
    if (i < NN) g_hist[i] = 0ull;
    if (i < 4)  g_vctr[i] = 0;
}

__global__ void k_hist(const int* __restrict__ ei, const float* __restrict__ ew) {
    int e = blockIdx.x * blockDim.x + threadIdx.x;
    if (e < EE) {
        int d = ei[EE + e];
        unsigned long long pk =
            (1ull << 32) | (unsigned long long)(unsigned)__float2uint_rn(ew[e] * 16777216.f);
        atomicAdd(&g_hist[d], pk);
    }
}

// single block, 1024 threads, 4 nodes/thread: exclusive scan of (cnt+1),
// emits self-loop edge at slot rowptr[v], pre-fills cursor = rowptr[v]+1.
__global__ void k_scan() {
    __shared__ int wtot[32];
    int tid = threadIdx.x, lane = tid & 31, wid = tid >> 5;
    int offset = 0;
    for (int base = 0; base < NN; base += 4096) {
        int v0 = base + tid * 4;
        int d0 = 0, d1 = 0, d2 = 0, d3 = 0;
        float lw0 = 0.f, lw1 = 0.f, lw2 = 0.f, lw3 = 0.f;
        if (v0 < NN) {
            unsigned long long h0 = g_hist[v0],     h1 = g_hist[v0 + 1];
            unsigned long long h2 = g_hist[v0 + 2], h3 = g_hist[v0 + 3];
            int c0 = (int)(h0 >> 32), c1 = (int)(h1 >> 32);
            int c2 = (int)(h2 >> 32), c3 = (int)(h3 >> 32);
            lw0 = (float)(unsigned)h0 * (1.f / 16777216.f) / fmaxf((float)c0, 1.f);
            lw1 = (float)(unsigned)h1 * (1.f / 16777216.f) / fmaxf((float)c1, 1.f);
            lw2 = (float)(unsigned)h2 * (1.f / 16777216.f) / fmaxf((float)c2, 1.f);
            lw3 = (float)(unsigned)h3 * (1.f / 16777216.f) / fmaxf((float)c3, 1.f);
            d0 = c0 + 1; d1 = c1 + 1; d2 = c2 + 1; d3 = c3 + 1;
        }
        int t = d0 + d1 + d2 + d3;
        int x = t;
        #pragma unroll
        for (int o = 1; o < 32; o <<= 1) {
            int y = __shfl_up_sync(0xffffffffu, x, o);
            if (lane >= o) x += y;
        }
        if (lane == 31) wtot[wid] = x;
        __syncthreads();
        if (wid == 0) {
            int s = wtot[lane];
            #pragma unroll
            for (int o = 1; o < 32; o <<= 1) {
                int y = __shfl_up_sync(0xffffffffu, s, o);
                if (lane >= o) s += y;
            }
            wtot[lane] = s;
        }
        __syncthreads();
        int pre   = (wid > 0) ? wtot[wid - 1] : 0;
        int total = wtot[31];
        int run = offset + pre + (x - t);
        if (v0 < NN) {
            g_rowptr[v0] = run;  g_cursor[v0] = run + 1;
            g_edge[run] = make_int2(v0 * 64, __float_as_int(lw0));          run += d0;
            g_rowptr[v0 + 1] = run;  g_cursor[v0 + 1] = run + 1;
            g_edge[run] = make_int2((v0 + 1) * 64, __float_as_int(lw1));    run += d1;
            g_rowptr[v0 + 2] = run;  g_cursor[v0 + 2] = run + 1;
            g_edge[run] = make_int2((v0 + 2) * 64, __float_as_int(lw2));    run += d2;
            g_rowptr[v0 + 3] = run;  g_cursor[v0 + 3] = run + 1;
            g_edge[run] = make_int2((v0 + 3) * 64, __float_as_int(lw3));
        }
        offset += total;
        __syncthreads();
    }
    if (tid == 0) g_rowptr[NN] = offset;
}

__global__ void k_scatter(const int* __restrict__ ei, const float* __restrict__ ew) {
    int i = blockIdx.x * blockDim.x + threadIdx.x;
    if (i < EE) {
        int s = ei[i], d = ei[EE + i];
        int p = atomicAdd(&g_cursor[d], 1);
        g_edge[p] = make_int2(s * 64, __float_as_int(ew[i]));
    }
}

// ---------------- weight prep: W[k][c] (KxN) -> img[c][k] (NxK fp16) ------
__device__ __forceinline__ void wprep_one(const float* __restrict__ W,
                                          __half* __restrict__ img,
                                          int e, int KOUT) {
    int c = e % KOUT;
    int k = e / KOUT;
    img[(size_t)c * 128 + k] = __float2half(W[(size_t)k * KOUT + c]);
}

__global__ void k_wprep(const float* __restrict__ Wl0, const float* __restrict__ Wr0,
                        const float* __restrict__ Wl1, const float* __restrict__ Wr1,
                        const float* __restrict__ Wl2, const float* __restrict__ Wr2) {
    int i = blockIdx.x * blockDim.x + threadIdx.x;
    if (i >= 4 * 16384 + 2 * 8192) return;
    if      (i < 16384) wprep_one(Wl0, g_wimg,          i,          128);
    else if (i < 32768) wprep_one(Wr0, g_wimg + 16384,  i - 16384,  128);
    else if (i < 49152) wprep_one(Wl1, g_wimg + 32768,  i - 32768,  128);
    else if (i < 65536) wprep_one(Wr1, g_wimg + 49152,  i - 49152,  128);
    else if (i < 73728) wprep_one(Wl2, g_wimg + 65536,  i - 65536,   64);
    else                wprep_one(Wr2, g_wimg + 73728,  i - 73728,   64);
}

// ---------------- HMMA dual GEMM ----------------
template <int KOUT>
__global__ void __launch_bounds__(256, 2)
k_gemm_hmma(const float* __restrict__ X,
            const __half* __restrict__ imgL, const __half* __restrict__ imgR,
            const float* __restrict__ bl, const float* __restrict__ br,
            __half* __restrict__ outl, float* __restrict__ outr) {
    constexpr int KIN = 128;
    constexpr int PH  = 136;             // smem pitch in halves (conflict-free)
    constexpr int NT  = KOUT / 8;        // n-tiles per pass

    extern __shared__ __half smem[];
    __half* sA  = smem;                  // 128 * PH
    __half* sBL = sA + 128 * PH;         // KOUT * PH
    __half* sBR = sBL + KOUT * PH;       // KOUT * PH

    int tid = threadIdx.x, wid = tid >> 5, lane = tid & 31;
    int nbase = blockIdx.x * 128;

    for (int idx = tid; idx < 128 * 64; idx += 256) {
        int r = idx >> 6, kp = idx & 63;
        int node = nbase + r;
        float2 v = make_float2(0.f, 0.f);
        if (node < NN) v = *(const float2*)&X[(size_t)node * KIN + 2 * kp];
        *(__half2*)&sA[r * PH + 2 * kp] = __floats2half2_rn(v.x, v.y);
    }
    for (int i = tid; i < KOUT * 16; i += 256) {
        int c = i >> 4, k8 = i & 15;
        *(uint4*)&sBL[c * PH + k8 * 8] = *(const uint4*)&imgL[(size_t)c * 128 + k8 * 8];
        *(uint4*)&sBR[c * PH + k8 * 8] = *(const uint4*)&imgR[(size_t)c * 128 + k8 * 8];
    }
    __syncthreads();

    uint32_t saA  = smem_to_u32(sA);
    uint32_t saBL = smem_to_u32(sBL);
    uint32_t saBR = smem_to_u32(sBR);

    int m0   = wid * 16;
    int lrow = lane & 15;
    int lcg  = lane >> 4;
    uint32_t aoff = (uint32_t)(((m0 + lrow) * PH + lcg * 8) * 2);
    uint32_t boff = (uint32_t)((lrow * PH + lcg * 8) * 2);

    int erow  = lane >> 2;
    int ecol0 = (lane & 3) * 2;
    int node0 = nbase + m0 + erow;
    int node1 = node0 + 8;

    // ---- pass 0: L ----
    {
        float acc[NT][4];
        #pragma unroll
        for (int n = 0; n < NT; n++)
            { acc[n][0] = acc[n][1] = acc[n][2] = acc[n][3] = 0.f; }
        #pragma unroll
        for (int k0 = 0; k0 < KIN; k0 += 16) {
            uint32_t a[4];
            ldsm4(a, saA + aoff + k0 * 2);
            #pragma unroll
            for (int nt = 0; nt < NT; nt += 2) {
                uint32_t b[4];
                ldsm4(b, saBL + boff + (uint32_t)((nt * 8 * PH + k0) * 2));
                mma16816(acc[nt],     a, b[0], b[2]);
                mma16816(acc[nt + 1], a, b[1], b[3]);
            }
        }
        #pragma unroll
        for (int nt = 0; nt < NT; nt++) {
            int c = nt * 8 + ecol0;
            float bv0 = bl[c], bv1 = bl[c + 1];
            if (node0 < NN)
                *(__half2*)&outl[(size_t)node0 * KOUT + c] =
                    __floats2half2_rn(acc[nt][0] + bv0, acc[nt][1] + bv1);
            if (node1 < NN)
                *(__half2*)&outl[(size_t)node1 * KOUT + c] =
                    __floats2half2_rn(acc[nt][2] + bv0, acc[nt][3] + bv1);
        }
    }
    // ---- pass 1: R ----
    {
        float acc[NT][4];
        #pragma unroll
        for (int n = 0; n < NT; n++)
            { acc[n][0] = acc[n][1] = acc[n][2] = acc[n][3] = 0.f; }
        #pragma unroll
        for (int k0 = 0; k0 < KIN; k0 += 16) {
            uint32_t a[4];
            ldsm4(a, saA + aoff + k0 * 2);
            #pragma unroll
            for (int nt = 0; nt < NT; nt += 2) {
                uint32_t b[4];
                ldsm4(b, saBR + boff + (uint32_t)((nt * 8 * PH + k0) * 2));
                mma16816(acc[nt],     a, b[0], b[2]);
                mma16816(acc[nt + 1], a, b[1], b[3]);
            }
        }
        #pragma unroll
        for (int nt = 0; nt < NT; nt++) {
            int c = nt * 8 + ecol0;
            float bv0 = br[c], bv1 = br[c + 1];
            if (node0 < NN) {
                float2 r0 = make_float2(acc[nt][0] + bv0, acc[nt][1] + bv1);
                *(float2*)&outr[(size_t)node0 * KOUT + c] = r0;
            }
            if (node1 < NN) {
                float2 r1 = make_float2(acc[nt][2] + bv0, acc[nt][3] + bv1);
                *(float2*)&outr[(size_t)node1 * KOUT + c] = r1;
            }
        }
    }
}

// ---------------- edge phase: persistent warps + atomic work queue --------
// Each warp grabs batches of 4 nodes; next grab issued before batch compute.
template <int D, int H, bool DO_ELU, int CTR>
__global__ void __launch_bounds__(256)
k_edge(const float* __restrict__ We, const float* __restrict__ att,
       const float* __restrict__ bias, float* __restrict__ out) {
    constexpr int CPL = D / 32;
    constexpr int G   = 32 / H;          // lanes per head group
    const unsigned FULL = 0xffffffffu;
    int lane = threadIdx.x & 31;
    int c0 = lane * CPL;

    float we[CPL], at[CPL], bi[CPL];
    #pragma unroll
    for (int j = 0; j < CPL; j++) {
        we[j] = We[c0 + j];
        at[j] = att[c0 + j];
        bi[j] = bias[c0 + j];
    }

    int base;
    if (lane == 0) base = atomicAdd(&g_vctr[CTR], 4);
    base = __shfl_sync(FULL, base, 0);

    while (base < NN) {
        int nxt_raw = 0;
        if (lane == 0) nxt_raw = atomicAdd(&g_vctr[CTR], 4);  // latency hidden

        int vend = base + 4 < NN ? base + 4 : NN;
        for (int v = base; v < vend; v++) {
            float b[CPL], acc[CPL];
            if (CPL == 4) {
                float4 t4 = *(const float4*)&g_xr[(size_t)v * D + c0];
                b[0] = t4.x; b[1] = t4.y; b[2] = t4.z; b[3] = t4.w;
            } else {
                float2 t2 = *(const float2*)&g_xr[(size_t)v * D + c0];
                b[0] = t2.x; b[1] = t2.y;
            }
            #pragma unroll
            for (int j = 0; j < CPL; j++) acc[j] = 0.f;

            float s = 0.f;
            int beg = g_rowptr[v], end = g_rowptr[v + 1];

            int2  ecur, enxt;
            uint2 xcur, xnxt;
            ecur = g_edge[beg];
            if (CPL == 4) {
                xcur = *(const uint2*)(g_xlh + ((size_t)ecur.x << 1) + c0);
            } else {
                xcur.x = *(const unsigned*)(g_xlh + (size_t)ecur.x + c0);
                xcur.y = 0;
            }

            for (int i = beg; i < end; i++) {
                if (i + 1 < end) {
                    enxt = g_edge[i + 1];
                    if (CPL == 4) {
                        xnxt = *(const uint2*)(g_xlh + ((size_t)enxt.x << 1) + c0);
                    } else {
                        xnxt.x = *(const unsigned*)(g_xlh + (size_t)enxt.x + c0);
                        xnxt.y = 0;
                    }
                }

                float wcur = __int_as_float(ecur.y);
                float a[CPL];
                {
                    float2 f0 = __half22float2(*(__half2*)&xcur.x);
                    a[0] = f0.x; a[1] = f0.y;
                    if (CPL == 4) {
                        float2 f1 = __half22float2(*(__half2*)&xcur.y);
                        a[2] = f1.x; a[3] = f1.y;
                    }
                }

                float t = 0.f;
                #pragma unroll
                for (int j = 0; j < CPL; j++) {
                    float e = fmaf(wcur, we[j], b[j]) + a[j];
                    e = e > 0.f ? e : 0.2f * e;          // leaky relu
                    t = fmaf(e, at[j], t);
                }
                #pragma unroll
                for (int o = 1; o < G; o <<= 1) t += __shfl_xor_sync(FULL, t, o);

                float p = __expf(fminf(t, 80.f));
                s += p;
                #pragma unroll
                for (int j = 0; j < CPL; j++) acc[j] = fmaf(p, a[j], acc[j]);

                ecur = enxt;
                xcur = xnxt;
            }

            float inv = 1.f / (s + 1e-16f);
            #pragma unroll
            for (int j = 0; j < CPL; j++) {
                float o = fmaf(acc[j], inv, bi[j]);
                if (DO_ELU) o = o > 0.f ? o : (__expf(o) - 1.f);
                out[(size_t)v * D + c0 + j] = o;
            }
        }
        base = __shfl_sync(FULL, nxt_raw, 0);
    }
}

// ---------------- launch ----------------
extern "C" void kernel_launch(void* const* d_in, const int* in_sizes, int n_in,
                              void* d_out, int out_size) {
    (void)in_sizes; (void)n_in; (void)out_size;
    const float* x    = (const float*)d_in[0];
    const int*   ei   = (const int*)  d_in[1];
    const float* ew   = (const float*)d_in[2];
    const float* Wl0  = (const float*)d_in[3];
    const float* bl0  = (const float*)d_in[4];
    const float* Wr0  = (const float*)d_in[5];
    const float* br0  = (const float*)d_in[6];
    const float* We0  = (const float*)d_in[7];
    const float* att0 = (const float*)d_in[8];
    const float* bias0= (const float*)d_in[9];
    const float* Wl1  = (const float*)d_in[10];
    const float* bl1  = (const float*)d_in[11];
    const float* Wr1  = (const float*)d_in[12];
    const float* br1  = (const float*)d_in[13];
    const float* We1  = (const float*)d_in[14];
    const float* att1 = (const float*)d_in[15];
    const float* bias1= (const float*)d_in[16];
    const float* Wl2  = (const float*)d_in[17];
    const float* bl2  = (const float*)d_in[18];
    const float* Wr2  = (const float*)d_in[19];
    const float* br2  = (const float*)d_in[20];
    const float* We2  = (const float*)d_in[21];
    const float* att2 = (const float*)d_in[22];
    const float* bias2= (const float*)d_in[23];
    float* out = (float*)d_out;

    __half *p_xl, *p_wimg; float *p_xr, *p_h;
    cudaGetSymbolAddress((void**)&p_xl,  g_xlh);
    cudaGetSymbolAddress((void**)&p_xr,  g_xr);
    cudaGetSymbolAddress((void**)&p_h,   g_h);
    cudaGetSymbolAddress((void**)&p_wimg, g_wimg);

    const int SM128 = (128 + 2 * 128) * 136 * 2;   // 104448 B
    const int SM64  = (128 + 2 * 64)  * 136 * 2;   //  69632 B
    cudaFuncSetAttribute(k_gemm_hmma<128>, cudaFuncAttributeMaxDynamicSharedMemorySize, SM128);
    cudaFuncSetAttribute(k_gemm_hmma<64>,  cudaFuncAttributeMaxDynamicSharedMemorySize, SM64);

    // CSR build + weight prep
    k_zero   <<<(NN + 255) / 256, 256>>>();
    k_hist   <<<(EE + 255) / 256, 256>>>(ei, ew);
    k_scan   <<<1, 1024>>>();
    k_scatter<<<(EE + 255) / 256, 256>>>(ei, ew);
    k_wprep  <<<(4 * 16384 + 2 * 8192 + 255) / 256, 256>>>(Wl0, Wr0, Wl1, Wr1, Wl2, Wr2);

    const int GEMM_GRID = (NN + 127) / 128;       // 391
    const int EDGE_GRID = 296;                    // persistent: 2368 warps

    // layer 0: x -> g_h (ELU)
    k_gemm_hmma<128><<<GEMM_GRID, 256, SM128>>>(x, p_wimg, p_wimg + 16384,
                                                bl0, br0, p_xl, p_xr);
    k_edge<128, 4, true, 0><<<EDGE_GRID, 256>>>(We0, att0, bias0, p_h);

    // layer 1: g_h -> g_h (ELU)
    k_gemm_hmma<128><<<GEMM_GRID, 256, SM128>>>(p_h, p_wimg + 32768, p_wimg + 49152,
                                                bl1, br1, p_xl, p_xr);
    k_edge<128, 4, true, 1><<<EDGE_GRID, 256>>>(We1, att1, bias1, p_h);

    // layer 2: g_h -> out (no ELU, H=1, C=64)
    k_gemm_hmma<64><<<GEMM_GRID, 256, SM64>>>(p_h, p_wimg + 65536, p_wimg + 73728,
                                              bl2, br2, p_xl, p_xr);
    k_edge<64, 1, false, 2><<<EDGE_GRID, 256>>>(We2, att2, bias2, out);
}

// round 13
// speedup vs baseline: 1.0222x; 1.0222x over previous
#include <cuda_runtime.h>
#include <cuda_fp16.h>
#include <math.h>
#include <cstdint>

#define NN   50000
#define EE   800000
#define ET   (NN + EE)     // 850000 edges incl. self loops
#define DHID 128
#define DOUT 64

// ---------------- device scratch (static, no allocation) ----------------
__device__ __align__(16) unsigned long long g_hist[NN];  // cnt<<32 | sumw*2^24
__device__ __align__(16) int   g_rowptr[NN + 1];
__device__ __align__(16) int   g_cursor[NN];
__device__ __align__(16) int2  g_edge[ET];          // (src*64, w bits)
__device__ __align__(16) __half g_xlh[NN * DHID];   // xl in fp16
__device__ __align__(16) float  g_xr[NN * DHID];
__device__ __align__(16) float  g_h [NN * DHID];
// pre-transposed fp16 weight images, row-major N x K (K=128)
__device__ __align__(16) __half g_wimg[4 * 16384 + 2 * 8192];

// ---------------- helpers ----------------
__device__ __forceinline__ uint32_t smem_to_u32(const void* p) {
    uint32_t a;
    asm("{ .reg .u64 t; cvta.to.shared.u64 t, %1; cvt.u32.u64 %0, t; }"
        : "=r"(a) : "l"(p));
    return a;
}
__device__ __forceinline__ void ldsm4(uint32_t* r, uint32_t addr) {
    asm volatile("ldmatrix.sync.aligned.m8n8.x4.shared.b16 {%0,%1,%2,%3}, [%4];"
        : "=r"(r[0]), "=r"(r[1]), "=r"(r[2]), "=r"(r[3]) : "r"(addr));
}
__device__ __forceinline__ void mma16816(float* d, const uint32_t* a,
                                         uint32_t b0, uint32_t b1) {
    asm volatile("mma.sync.aligned.m16n8k16.row.col.f32.f16.f16.f32 "
        "{%0,%1,%2,%3}, {%4,%5,%6,%7}, {%8,%9}, {%0,%1,%2,%3};"
        : "+f"(d[0]), "+f"(d[1]), "+f"(d[2]), "+f"(d[3])
        : "r"(a[0]), "r"(a[1]), "r"(a[2]), "r"(a[3]), "r"(b0), "r"(b1));
}

// ---------------- CSR build ----------------
__global__ void k_zero() {
    int i = blockIdx.x * blockDim.x + threadIdx.x;
    if (i < NN) g_hist[i] = 0ull;
}

__global__ void k_hist(const int* __restrict__ ei, const float* __restrict__ ew) {
    int e = blockIdx.x * blockDim.x + threadIdx.x;
    if (e < EE) {
        int d = ei[EE + e];
        unsigned long long pk =
            (1ull << 32) | (unsigned long long)(unsigned)__float2uint_rn(ew[e] * 16777216.f);
        atomicAdd(&g_hist[d], pk);
    }
}

// single block, 1024 threads, 4 nodes/thread: exclusive scan of (cnt+1),
// emits self-loop edge at slot rowptr[v], pre-fills cursor = rowptr[v]+1.
__global__ void k_scan() {
    __shared__ int wtot[32];
    int tid = threadIdx.x, lane = tid & 31, wid = tid >> 5;
    int offset = 0;
    for (int base = 0; base < NN; base += 4096) {
        int v0 = base + tid * 4;
        int d0 = 0, d1 = 0, d2 = 0, d3 = 0;
        float lw0 = 0.f, lw1 = 0.f, lw2 = 0.f, lw3 = 0.f;
        if (v0 < NN) {
            unsigned long long h0 = g_hist[v0],     h1 = g_hist[v0 + 1];
            unsigned long long h2 = g_hist[v0 + 2], h3 = g_hist[v0 + 3];
            int c0 = (int)(h0 >> 32), c1 = (int)(h1 >> 32);
            int c2 = (int)(h2 >> 32), c3 = (int)(h3 >> 32);
            lw0 = (float)(unsigned)h0 * (1.f / 16777216.f) / fmaxf((float)c0, 1.f);
            lw1 = (float)(unsigned)h1 * (1.f / 16777216.f) / fmaxf((float)c1, 1.f);
            lw2 = (float)(unsigned)h2 * (1.f / 16777216.f) / fmaxf((float)c2, 1.f);
            lw3 = (float)(unsigned)h3 * (1.f / 16777216.f) / fmaxf((float)c3, 1.f);
            d0 = c0 + 1; d1 = c1 + 1; d2 = c2 + 1; d3 = c3 + 1;
        }
        int t = d0 + d1 + d2 + d3;
        int x = t;
        #pragma unroll
        for (int o = 1; o < 32; o <<= 1) {
            int y = __shfl_up_sync(0xffffffffu, x, o);
            if (lane >= o) x += y;
        }
        if (lane == 31) wtot[wid] = x;
        __syncthreads();
        if (wid == 0) {
            int s = wtot[lane];
            #pragma unroll
            for (int o = 1; o < 32; o <<= 1) {
                int y = __shfl_up_sync(0xffffffffu, s, o);
                if (lane >= o) s += y;
            }
            wtot[lane] = s;
        }
        __syncthreads();
        int pre   = (wid > 0) ? wtot[wid - 1] : 0;
        int total = wtot[31];
        int run = offset + pre + (x - t);
        if (v0 < NN) {
            g_rowptr[v0] = run;  g_cursor[v0] = run + 1;
            g_edge[run] = make_int2(v0 * 64, __float_as_int(lw0));          run += d0;
            g_rowptr[v0 + 1] = run;  g_cursor[v0 + 1] = run + 1;
            g_edge[run] = make_int2((v0 + 1) * 64, __float_as_int(lw1));    run += d1;
            g_rowptr[v0 + 2] = run;  g_cursor[v0 + 2] = run + 1;
            g_edge[run] = make_int2((v0 + 2) * 64, __float_as_int(lw2));    run += d2;
            g_rowptr[v0 + 3] = run;  g_cursor[v0 + 3] = run + 1;
            g_edge[run] = make_int2((v0 + 3) * 64, __float_as_int(lw3));
        }
        offset += total;
        __syncthreads();
    }
    if (tid == 0) g_rowptr[NN] = offset;
}

__global__ void k_scatter(const int* __restrict__ ei, const float* __restrict__ ew) {
    int i = blockIdx.x * blockDim.x + threadIdx.x;
    if (i < EE) {
        int s = ei[i], d = ei[EE + i];
        int p = atomicAdd(&g_cursor[d], 1);
        g_edge[p] = make_int2(s * 64, __float_as_int(ew[i]));
    }
}

// ---------------- weight prep: W[k][c] (KxN) -> img[c][k] (NxK fp16) ------
__device__ __forceinline__ void wprep_one(const float* __restrict__ W,
                                          __half* __restrict__ img,
                                          int e, int KOUT) {
    int c = e % KOUT;
    int k = e / KOUT;
    img[(size_t)c * 128 + k] = __float2half(W[(size_t)k * KOUT + c]);
}

__global__ void k_wprep(const float* __restrict__ Wl0, const float* __restrict__ Wr0,
                        const float* __restrict__ Wl1, const float* __restrict__ Wr1,
                        const float* __restrict__ Wl2, const float* __restrict__ Wr2) {
    int i = blockIdx.x * blockDim.x + threadIdx.x;
    if (i >= 4 * 16384 + 2 * 8192) return;
    if      (i < 16384) wprep_one(Wl0, g_wimg,          i,          128);
    else if (i < 32768) wprep_one(Wr0, g_wimg + 16384,  i - 16384,  128);
    else if (i < 49152) wprep_one(Wl1, g_wimg + 32768,  i - 32768,  128);
    else if (i < 65536) wprep_one(Wr1, g_wimg + 49152,  i - 49152,  128);
    else if (i < 73728) wprep_one(Wl2, g_wimg + 65536,  i - 65536,   64);
    else                wprep_one(Wr2, g_wimg + 73728,  i - 73728,   64);
}

// ---------------- HMMA dual GEMM ----------------
template <int KOUT>
__global__ void __launch_bounds__(256, 2)
k_gemm_hmma(const float* __restrict__ X,
            const __half* __restrict__ imgL, const __half* __restrict__ imgR,
            const float* __restrict__ bl, const float* __restrict__ br,
            __half* __restrict__ outl, float* __restrict__ outr) {
    constexpr int KIN = 128;
    constexpr int PH  = 136;             // smem pitch in halves (conflict-free)
    constexpr int NT  = KOUT / 8;        // n-tiles per pass

    extern __shared__ __half smem[];
    __half* sA  = smem;                  // 128 * PH
    __half* sBL = sA + 128 * PH;         // KOUT * PH
    __half* sBR = sBL + KOUT * PH;       // KOUT * PH

    int tid = threadIdx.x, wid = tid >> 5, lane = tid & 31;
    int nbase = blockIdx.x * 128;

    for (int idx = tid; idx < 128 * 64; idx += 256) {
        int r = idx >> 6, kp = idx & 63;
        int node = nbase + r;
        float2 v = make_float2(0.f, 0.f);
        if (node < NN) v = *(const float2*)&X[(size_t)node * KIN + 2 * kp];
        *(__half2*)&sA[r * PH + 2 * kp] = __floats2half2_rn(v.x, v.y);
    }
    for (int i = tid; i < KOUT * 16; i += 256) {
        int c = i >> 4, k8 = i & 15;
        *(uint4*)&sBL[c * PH + k8 * 8] = *(const uint4*)&imgL[(size_t)c * 128 + k8 * 8];
        *(uint4*)&sBR[c * PH + k8 * 8] = *(const uint4*)&imgR[(size_t)c * 128 + k8 * 8];
    }
    __syncthreads();

    uint32_t saA  = smem_to_u32(sA);
    uint32_t saBL = smem_to_u32(sBL);
    uint32_t saBR = smem_to_u32(sBR);

    int m0   = wid * 16;
    int lrow = lane & 15;
    int lcg  = lane >> 4;
    uint32_t aoff = (uint32_t)(((m0 + lrow) * PH + lcg * 8) * 2);
    uint32_t boff = (uint32_t)((lrow * PH + lcg * 8) * 2);

    int erow  = lane >> 2;
    int ecol0 = (lane & 3) * 2;
    int node0 = nbase + m0 + erow;
    int node1 = node0 + 8;

    // ---- pass 0: L ----
    {
        float acc[NT][4];
        #pragma unroll
        for (int n = 0; n < NT; n++)
            { acc[n][0] = acc[n][1] = acc[n][2] = acc[n][3] = 0.f; }
        #pragma unroll
        for (int k0 = 0; k0 < KIN; k0 += 16) {
            uint32_t a[4];
            ldsm4(a, saA + aoff + k0 * 2);
            #pragma unroll
            for (int nt = 0; nt < NT; nt += 2) {
                uint32_t b[4];
                ldsm4(b, saBL + boff + (uint32_t)((nt * 8 * PH + k0) * 2));
                mma16816(acc[nt],     a, b[0], b[2]);
                mma16816(acc[nt + 1], a, b[1], b[3]);
            }
        }
        #pragma unroll
        for (int nt = 0; nt < NT; nt++) {
            int c = nt * 8 + ecol0;
            float bv0 = bl[c], bv1 = bl[c + 1];
            if (node0 < NN)
                *(__half2*)&outl[(size_t)node0 * KOUT + c] =
                    __floats2half2_rn(acc[nt][0] + bv0, acc[nt][1] + bv1);
            if (node1 < NN)
                *(__half2*)&outl[(size_t)node1 * KOUT + c] =
                    __floats2half2_rn(acc[nt][2] + bv0, acc[nt][3] + bv1);
        }
    }
    // ---- pass 1: R ----
    {
        float acc[NT][4];
        #pragma unroll
        for (int n = 0; n < NT; n++)
            { acc[n][0] = acc[n][1] = acc[n][2] = acc[n][3] = 0.f; }
        #pragma unroll
        for (int k0 = 0; k0 < KIN; k0 += 16) {
            uint32_t a[4];
            ldsm4(a, saA + aoff + k0 * 2);
            #pragma unroll
            for (int nt = 0; nt < NT; nt += 2) {
                uint32_t b[4];
                ldsm4(b, saBR + boff + (uint32_t)((nt * 8 * PH + k0) * 2));
                mma16816(acc[nt],     a, b[0], b[2]);
                mma16816(acc[nt + 1], a, b[1], b[3]);
            }
        }
        #pragma unroll
        for (int nt = 0; nt < NT; nt++) {
            int c = nt * 8 + ecol0;
            float bv0 = br[c], bv1 = br[c + 1];
            if (node0 < NN) {
                float2 r0 = make_float2(acc[nt][0] + bv0, acc[nt][1] + bv1);
                *(float2*)&outr[(size_t)node0 * KOUT + c] = r0;
            }
            if (node1 < NN) {
                float2 r1 = make_float2(acc[nt][2] + bv0, acc[nt][3] + bv1);
                *(float2*)&outr[(size_t)node1 * KOUT + c] = r1;
            }
        }
    }
}

// ---------------- edge phase: persistent grid-stride warps ----------------
// 2368 warps; warp w handles nodes w, w+2368, ... (~21 nodes, sum-Poisson
// balanced to ~5%). No atomics, no CTA-granularity tail.
#define EDGE_CTAS  296
#define EDGE_WARPS (EDGE_CTAS * 8)

template <int D, int H, bool DO_ELU>
__global__ void __launch_bounds__(256)
k_edge(const float* __restrict__ We, const float* __restrict__ att,
       const float* __restrict__ bias, float* __restrict__ out) {
    constexpr int CPL = D / 32;
    constexpr int G   = 32 / H;          // lanes per head group
    const unsigned FULL = 0xffffffffu;
    int gw   = (blockIdx.x * blockDim.x + threadIdx.x) >> 5;
    int lane = threadIdx.x & 31;
    int c0 = lane * CPL;

    float we[CPL], at[CPL], bi[CPL];
    #pragma unroll
    for (int j = 0; j < CPL; j++) {
        we[j] = We[c0 + j];
        at[j] = att[c0 + j];
        bi[j] = bias[c0 + j];
    }

    for (int v = gw; v < NN; v += EDGE_WARPS) {
        float b[CPL], acc[CPL];
        if (CPL == 4) {
            float4 t4 = *(const float4*)&g_xr[(size_t)v * D + c0];
            b[0] = t4.x; b[1] = t4.y; b[2] = t4.z; b[3] = t4.w;
        } else {
            float2 t2 = *(const float2*)&g_xr[(size_t)v * D + c0];
            b[0] = t2.x; b[1] = t2.y;
        }
        #pragma unroll
        for (int j = 0; j < CPL; j++) acc[j] = 0.f;

        float s = 0.f;
        int beg = g_rowptr[v], end = g_rowptr[v + 1];

        int2  ecur, enxt;
        uint2 xcur, xnxt;
        ecur = g_edge[beg];
        if (CPL == 4) {
            xcur = *(const uint2*)(g_xlh + ((size_t)ecur.x << 1) + c0);
        } else {
            xcur.x = *(const unsigned*)(g_xlh + (size_t)ecur.x + c0);
            xcur.y = 0;
        }

        for (int i = beg; i < end; i++) {
            if (i + 1 < end) {
                enxt = g_edge[i + 1];
                if (CPL == 4) {
                    xnxt = *(const uint2*)(g_xlh + ((size_t)enxt.x << 1) + c0);
                } else {
                    xnxt.x = *(const unsigned*)(g_xlh + (size_t)enxt.x + c0);
                    xnxt.y = 0;
                }
            }

            float wcur = __int_as_float(ecur.y);
            float a[CPL];
            {
                float2 f0 = __half22float2(*(__half2*)&xcur.x);
                a[0] = f0.x; a[1] = f0.y;
                if (CPL == 4) {
                    float2 f1 = __half22float2(*(__half2*)&xcur.y);
                    a[2] = f1.x; a[3] = f1.y;
                }
            }

            float t = 0.f;
            #pragma unroll
            for (int j = 0; j < CPL; j++) {
                float e = fmaf(wcur, we[j], b[j]) + a[j];
                e = e > 0.f ? e : 0.2f * e;          // leaky relu
                t = fmaf(e, at[j], t);
            }
            #pragma unroll
            for (int o = 1; o < G; o <<= 1) t += __shfl_xor_sync(FULL, t, o);

            float p = __expf(fminf(t, 80.f));
            s += p;
            #pragma unroll
            for (int j = 0; j < CPL; j++) acc[j] = fmaf(p, a[j], acc[j]);

            ecur = enxt;
            xcur = xnxt;
        }

        float inv = 1.f / (s + 1e-16f);
        #pragma unroll
        for (int j = 0; j < CPL; j++) {
            float o = fmaf(acc[j], inv, bi[j]);
            if (DO_ELU) o = o > 0.f ? o : (__expf(o) - 1.f);
            out[(size_t)v * D + c0 + j] = o;
        }
    }
}

// ---------------- launch ----------------
extern "C" void kernel_launch(void* const* d_in, const int* in_sizes, int n_in,
                              void* d_out, int out_size) {
    (void)in_sizes; (void)n_in; (void)out_size;
    const float* x    = (const float*)d_in[0];
    const int*   ei   = (const int*)  d_in[1];
    const float* ew   = (const float*)d_in[2];
    const float* Wl0  = (const float*)d_in[3];
    const float* bl0  = (const float*)d_in[4];
    const float* Wr0  = (const float*)d_in[5];
    const float* br0  = (const float*)d_in[6];
    const float* We0  = (const float*)d_in[7];
    const float* att0 = (const float*)d_in[8];
    const float* bias0= (const float*)d_in[9];
    const float* Wl1  = (const float*)d_in[10];
    const float* bl1  = (const float*)d_in[11];
    const float* Wr1  = (const float*)d_in[12];
    const float* br1  = (const float*)d_in[13];
    const float* We1  = (const float*)d_in[14];
    const float* att1 = (const float*)d_in[15];
    const float* bias1= (const float*)d_in[16];
    const float* Wl2  = (const float*)d_in[17];
    const float* bl2  = (const float*)d_in[18];
    const float* Wr2  = (const float*)d_in[19];
    const float* br2  = (const float*)d_in[20];
    const float* We2  = (const float*)d_in[21];
    const float* att2 = (const float*)d_in[22];
    const float* bias2= (const float*)d_in[23];
    float* out = (float*)d_out;

    __half *p_xl, *p_wimg; float *p_xr, *p_h;
    cudaGetSymbolAddress((void**)&p_xl,  g_xlh);
    cudaGetSymbolAddress((void**)&p_xr,  g_xr);
    cudaGetSymbolAddress((void**)&p_h,   g_h);
    cudaGetSymbolAddress((void**)&p_wimg, g_wimg);

    const int SM128 = (128 + 2 * 128) * 136 * 2;   // 104448 B
    const int SM64  = (128 + 2 * 64)  * 136 * 2;   //  69632 B
    cudaFuncSetAttribute(k_gemm_hmma<128>, cudaFuncAttributeMaxDynamicSharedMemorySize, SM128);
    cudaFuncSetAttribute(k_gemm_hmma<64>,  cudaFuncAttributeMaxDynamicSharedMemorySize, SM64);

    // CSR build + weight prep
    k_zero   <<<(NN + 255) / 256, 256>>>();
    k_hist   <<<(EE + 255) / 256, 256>>>(ei, ew);
    k_scan   <<<1, 1024>>>();
    k_scatter<<<(EE + 255) / 256, 256>>>(ei, ew);
    k_wprep  <<<(4 * 16384 + 2 * 8192 + 255) / 256, 256>>>(Wl0, Wr0, Wl1, Wr1, Wl2, Wr2);

    const int GEMM_GRID = (NN + 127) / 128;       // 391

    // layer 0: x -> g_h (ELU)
    k_gemm_hmma<128><<<GEMM_GRID, 256, SM128>>>(x, p_wimg, p_wimg + 16384,
                                                bl0, br0, p_xl, p_xr);
    k_edge<128, 4, true><<<EDGE_CTAS, 256>>>(We0, att0, bias0, p_h);

    // layer 1: g_h -> g_h (ELU)
    k_gemm_hmma<128><<<GEMM_GRID, 256, SM128>>>(p_h, p_wimg + 32768, p_wimg + 49152,
                                                bl1, br1, p_xl, p_xr);
    k_edge<128, 4, true><<<EDGE_CTAS, 256>>>(We1, att1, bias1, p_h);

    // layer 2: g_h -> out (no ELU, H=1, C=64)
    k_gemm_hmma<64><<<GEMM_GRID, 256, SM64>>>(p_h, p_wimg + 65536, p_wimg + 73728,
                                              bl2, br2, p_xl, p_xr);
    k_edge<64, 1, false><<<EDGE_CTAS, 256>>>(We2, att2, bias2, out);
}

// round 17
// speedup vs baseline: 1.6507x; 1.6149x over previous
#include <cuda_runtime.h>
#include <cuda_fp16.h>
#include <math.h>
#include <cstdint>

#define NN   50000
#define EE   800000
#define ET   (NN + EE)     // 850000 edges incl. self loops
#define DHID 128
#define DOUT 64

// ---------------- device scratch (static, no allocation) ----------------
__device__ __align__(16) unsigned long long g_hist[NN];  // cnt<<32 | sumw*2^24
__device__ __align__(16) int   g_rowptr[NN + 1];
__device__ __align__(16) int   g_cursor[NN];
__device__ __align__(16) int2  g_edge[ET];          // (src*64, w bits)
__device__ __align__(16) __half g_xlh[NN * DHID];   // xl in fp16
__device__ __align__(16) float  g_xr[NN * DHID];
__device__ __align__(16) float  g_h [NN * DHID];
// pre-transposed fp16 weight images, row-major N x K (K=128)
__device__ __align__(16) __half g_wimg[4 * 16384 + 2 * 8192];

// ---------------- helpers ----------------
__device__ __forceinline__ uint32_t smem_to_u32(const void* p) {
    uint32_t a;
    asm("{ .reg .u64 t; cvta.to.shared.u64 t, %1; cvt.u32.u64 %0, t; }"
        : "=r"(a) : "l"(p));
    return a;
}
__device__ __forceinline__ void ldsm4(uint32_t* r, uint32_t addr) {
    asm volatile("ldmatrix.sync.aligned.m8n8.x4.shared.b16 {%0,%1,%2,%3}, [%4];"
        : "=r"(r[0]), "=r"(r[1]), "=r"(r[2]), "=r"(r[3]) : "r"(addr));
}
__device__ __forceinline__ void mma16816(float* d, const uint32_t* a,
                                         uint32_t b0, uint32_t b1) {
    asm volatile("mma.sync.aligned.m16n8k16.row.col.f32.f16.f16.f32 "
        "{%0,%1,%2,%3}, {%4,%5,%6,%7}, {%8,%9}, {%0,%1,%2,%3};"
        : "+f"(d[0]), "+f"(d[1]), "+f"(d[2]), "+f"(d[3])
        : "r"(a[0]), "r"(a[1]), "r"(a[2]), "r"(a[3]), "r"(b0), "r"(b1));
}

// ---------------- CSR build ----------------
__global__ void k_zero() {
    int i = blockIdx.x * blockDim.x + threadIdx.x;
    if (i < NN) g_hist[i] = 0ull;
}

__global__ void k_hist(const int* __restrict__ ei, const float* __restrict__ ew) {
    int e = blockIdx.x * blockDim.x + threadIdx.x;
    if (e < EE) {
        int d = ei[EE + e];
        unsigned long long pk =
            (1ull << 32) | (unsigned long long)(unsigned)__float2uint_rn(ew[e] * 16777216.f);
        atomicAdd(&g_hist[d], pk);
    }
}

// single block, 1024 threads, 4 nodes/thread: exclusive scan of (cnt+1),
// emits self-loop edge at slot rowptr[v], pre-fills cursor = rowptr[v]+1.
__global__ void k_scan() {
    __shared__ int wtot[32];
    int tid = threadIdx.x, lane = tid & 31, wid = tid >> 5;
    int offset = 0;
    for (int base = 0; base < NN; base += 4096) {
        int v0 = base + tid * 4;
        int d0 = 0, d1 = 0, d2 = 0, d3 = 0;
        float lw0 = 0.f, lw1 = 0.f, lw2 = 0.f, lw3 = 0.f;
        if (v0 < NN) {
            unsigned long long h0 = g_hist[v0],     h1 = g_hist[v0 + 1];
            unsigned long long h2 = g_hist[v0 + 2], h3 = g_hist[v0 + 3];
            int c0 = (int)(h0 >> 32), c1 = (int)(h1 >> 32);
            int c2 = (int)(h2 >> 32), c3 = (int)(h3 >> 32);
            lw0 = (float)(unsigned)h0 * (1.f / 16777216.f) / fmaxf((float)c0, 1.f);
            lw1 = (float)(unsigned)h1 * (1.f / 16777216.f) / fmaxf((float)c1, 1.f);
            lw2 = (float)(unsigned)h2 * (1.f / 16777216.f) / fmaxf((float)c2, 1.f);
            lw3 = (float)(unsigned)h3 * (1.f / 16777216.f) / fmaxf((float)c3, 1.f);
            d0 = c0 + 1; d1 = c1 + 1; d2 = c2 + 1; d3 = c3 + 1;
        }
        int t = d0 + d1 + d2 + d3;
        int x = t;
        #pragma unroll
        for (int o = 1; o < 32; o <<= 1) {
            int y = __shfl_up_sync(0xffffffffu, x, o);
            if (lane >= o) x += y;
        }
        if (lane == 31) wtot[wid] = x;
        __syncthreads();
        if (wid == 0) {
            int s = wtot[lane];
            #pragma unroll
            for (int o = 1; o < 32; o <<= 1) {
                int y = __shfl_up_sync(0xffffffffu, s, o);
                if (lane >= o) s += y;
            }
            wtot[lane] = s;
        }
        __syncthreads();
        int pre   = (wid > 0) ? wtot[wid - 1] : 0;
        int total = wtot[31];
        int run = offset + pre + (x - t);
        if (v0 < NN) {
            g_rowptr[v0] = run;  g_cursor[v0] = run + 1;
            g_edge[run] = make_int2(v0 * 64, __float_as_int(lw0));          run += d0;
            g_rowptr[v0 + 1] = run;  g_cursor[v0 + 1] = run + 1;
            g_edge[run] = make_int2((v0 + 1) * 64, __float_as_int(lw1));    run += d1;
            g_rowptr[v0 + 2] = run;  g_cursor[v0 + 2] = run + 1;
            g_edge[run] = make_int2((v0 + 2) * 64, __float_as_int(lw2));    run += d2;
            g_rowptr[v0 + 3] = run;  g_cursor[v0 + 3] = run + 1;
            g_edge[run] = make_int2((v0 + 3) * 64, __float_as_int(lw3));
        }
        offset += total;
        __syncthreads();
    }
    if (tid == 0) g_rowptr[NN] = offset;
}

__global__ void k_scatter(const int* __restrict__ ei, const float* __restrict__ ew) {
    int i = blockIdx.x * blockDim.x + threadIdx.x;
    if (i < EE) {
        int s = ei[i], d = ei[EE + i];
        int p = atomicAdd(&g_cursor[d], 1);
        g_edge[p] = make_int2(s * 64, __float_as_int(ew[i]));
    }
}

// ---------------- weight prep: W[k][c] (KxN) -> img[c][k] (NxK fp16) ------
__device__ __forceinline__ void wprep_one(const float* __restrict__ W,
                                          __half* __restrict__ img,
                                          int e, int KOUT) {
    int c = e % KOUT;
    int k = e / KOUT;
    img[(size_t)c * 128 + k] = __float2half(W[(size_t)k * KOUT + c]);
}

__global__ void k_wprep(const float* __restrict__ Wl0, const float* __restrict__ Wr0,
                        const float* __restrict__ Wl1, const float* __restrict__ Wr1,
                        const float* __restrict__ Wl2, const float* __restrict__ Wr2) {
    int i = blockIdx.x * blockDim.x + threadIdx.x;
    if (i >= 4 * 16384 + 2 * 8192) return;
    if      (i < 16384) wprep_one(Wl0, g_wimg,          i,          128);
    else if (i < 32768) wprep_one(Wr0, g_wimg + 16384,  i - 16384,  128);
    else if (i < 49152) wprep_one(Wl1, g_wimg + 32768,  i - 32768,  128);
    else if (i < 65536) wprep_one(Wr1, g_wimg + 49152,  i - 49152,  128);
    else if (i < 73728) wprep_one(Wl2, g_wimg + 65536,  i - 65536,   64);
    else                wprep_one(Wr2, g_wimg + 73728,  i - 73728,   64);
}

// ---------------- HMMA dual GEMM ----------------
template <int KOUT>
__global__ void __launch_bounds__(256, 2)
k_gemm_hmma(const float* __restrict__ X,
            const __half* __restrict__ imgL, const __half* __restrict__ imgR,
            const float* __restrict__ bl, const float* __restrict__ br,
            __half* __restrict__ outl, float* __restrict__ outr) {
    constexpr int KIN = 128;
    constexpr int PH  = 136;             // smem pitch in halves (conflict-free)
    constexpr int NT  = KOUT / 8;        // n-tiles per pass

    extern __shared__ __half smem[];
    __half* sA  = smem;                  // 128 * PH
    __half* sBL = sA + 128 * PH;         // KOUT * PH
    __half* sBR = sBL + KOUT * PH;       // KOUT * PH

    int tid = threadIdx.x, wid = tid >> 5, lane = tid & 31;
    int nbase = blockIdx.x * 128;

    for (int idx = tid; idx < 128 * 64; idx += 256) {
        int r = idx >> 6, kp = idx & 63;
        int node = nbase + r;
        float2 v = make_float2(0.f, 0.f);
        if (node < NN) v = *(const float2*)&X[(size_t)node * KIN + 2 * kp];
        *(__half2*)&sA[r * PH + 2 * kp] = __floats2half2_rn(v.x, v.y);
    }
    for (int i = tid; i < KOUT * 16; i += 256) {
        int c = i >> 4, k8 = i & 15;
        *(uint4*)&sBL[c * PH + k8 * 8] = *(const uint4*)&imgL[(size_t)c * 128 + k8 * 8];
        *(uint4*)&sBR[c * PH + k8 * 8] = *(const uint4*)&imgR[(size_t)c * 128 + k8 * 8];
    }
    __syncthreads();

    uint32_t saA  = smem_to_u32(sA);
    uint32_t saBL = smem_to_u32(sBL);
    uint32_t saBR = smem_to_u32(sBR);

    int m0   = wid * 16;
    int lrow = lane & 15;
    int lcg  = lane >> 4;
    uint32_t aoff = (uint32_t)(((m0 + lrow) * PH + lcg * 8) * 2);
    uint32_t boff = (uint32_t)((lrow * PH + lcg * 8) * 2);

    int erow  = lane >> 2;
    int ecol0 = (lane & 3) * 2;
    int node0 = nbase + m0 + erow;
    int node1 = node0 + 8;

    // ---- pass 0: L ----
    {
        float acc[NT][4];
        #pragma unroll
        for (int n = 0; n < NT; n++)
            { acc[n][0] = acc[n][1] = acc[n][2] = acc[n][3] = 0.f; }
        #pragma unroll
        for (int k0 = 0; k0 < KIN; k0 += 16) {
            uint32_t a[4];
            ldsm4(a, saA + aoff + k0 * 2);
            #pragma unroll
            for (int nt = 0; nt < NT; nt += 2) {
                uint32_t b[4];
                ldsm4(b, saBL + boff + (uint32_t)((nt * 8 * PH + k0) * 2));
                mma16816(acc[nt],     a, b[0], b[2]);
                mma16816(acc[nt + 1], a, b[1], b[3]);
            }
        }
        #pragma unroll
        for (int nt = 0; nt < NT; nt++) {
            int c = nt * 8 + ecol0;
            float bv0 = bl[c], bv1 = bl[c + 1];
            if (node0 < NN)
                *(__half2*)&outl[(size_t)node0 * KOUT + c] =
                    __floats2half2_rn(acc[nt][0] + bv0, acc[nt][1] + bv1);
            if (node1 < NN)
                *(__half2*)&outl[(size_t)node1 * KOUT + c] =
                    __floats2half2_rn(acc[nt][2] + bv0, acc[nt][3] + bv1);
        }
    }
    // ---- pass 1: R ----
    {
        float acc[NT][4];
        #pragma unroll
        for (int n = 0; n < NT; n++)
            { acc[n][0] = acc[n][1] = acc[n][2] = acc[n][3] = 0.f; }
        #pragma unroll
        for (int k0 = 0; k0 < KIN; k0 += 16) {
            uint32_t a[4];
            ldsm4(a, saA + aoff + k0 * 2);
            #pragma unroll
            for (int nt = 0; nt < NT; nt += 2) {
                uint32_t b[4];
                ldsm4(b, saBR + boff + (uint32_t)((nt * 8 * PH + k0) * 2));
                mma16816(acc[nt],     a, b[0], b[2]);
                mma16816(acc[nt + 1], a, b[1], b[3]);
            }
        }
        #pragma unroll
        for (int nt = 0; nt < NT; nt++) {
            int c = nt * 8 + ecol0;
            float bv0 = br[c], bv1 = br[c + 1];
            if (node0 < NN) {
                float2 r0 = make_float2(acc[nt][0] + bv0, acc[nt][1] + bv1);
                *(float2*)&outr[(size_t)node0 * KOUT + c] = r0;
            }
            if (node1 < NN) {
                float2 r1 = make_float2(acc[nt][2] + bv0, acc[nt][3] + bv1);
                *(float2*)&outr[(size_t)node1 * KOUT + c] = r1;
            }
        }
    }
}

// ---------------- edge phase: warp per node, 64-thread CTAs ---------------
// Small CTAs shrink the max-of-k Poisson retire penalty (k=8 -> k=2).
template <int D, int H, bool DO_ELU>
__global__ void __launch_bounds__(64)
k_edge(const float* __restrict__ We, const float* __restrict__ att,
       const float* __restrict__ bias, float* __restrict__ out) {
    constexpr int CPL = D / 32;
    constexpr int G   = 32 / H;          // lanes per head group
    const unsigned FULL = 0xffffffffu;
    int gw   = (blockIdx.x * blockDim.x + threadIdx.x) >> 5;
    int lane = threadIdx.x & 31;
    if (gw >= NN) return;
    int v  = gw;
    int c0 = lane * CPL;

    float b[CPL], we[CPL], at[CPL], acc[CPL];
    if (CPL == 4) {
        float4 t4 = *(const float4*)&g_xr[(size_t)v * D + c0];
        b[0] = t4.x; b[1] = t4.y; b[2] = t4.z; b[3] = t4.w;
    } else {
        float2 t2 = *(const float2*)&g_xr[(size_t)v * D + c0];
        b[0] = t2.x; b[1] = t2.y;
    }
    #pragma unroll
    for (int j = 0; j < CPL; j++) {
        we[j]  = We[c0 + j];
        at[j]  = att[c0 + j];
        acc[j] = 0.f;
    }

    float s = 0.f;
    int beg = g_rowptr[v], end = g_rowptr[v + 1];

    int2  ecur, enxt;
    uint2 xcur, xnxt;
    ecur = g_edge[beg];
    if (CPL == 4) {
        xcur = *(const uint2*)(g_xlh + ((size_t)ecur.x << 1) + c0);
    } else {
        xcur.x = *(const unsigned*)(g_xlh + (size_t)ecur.x + c0);
        xcur.y = 0;
    }

    for (int i = beg; i < end; i++) {
        if (i + 1 < end) {
            enxt = g_edge[i + 1];
            if (CPL == 4) {
                xnxt = *(const uint2*)(g_xlh + ((size_t)enxt.x << 1) + c0);
            } else {
                xnxt.x = *(const unsigned*)(g_xlh + (size_t)enxt.x + c0);
                xnxt.y = 0;
            }
        }

        float wcur = __int_as_float(ecur.y);
        float a[CPL];
        {
            float2 f0 = __half22float2(*(__half2*)&xcur.x);
            a[0] = f0.x; a[1] = f0.y;
            if (CPL == 4) {
                float2 f1 = __half22float2(*(__half2*)&xcur.y);
                a[2] = f1.x; a[3] = f1.y;
            }
        }

        float t = 0.f;
        #pragma unroll
        for (int j = 0; j < CPL; j++) {
            float e = fmaf(wcur, we[j], b[j]) + a[j];
            e = e > 0.f ? e : 0.2f * e;          // leaky relu
            t = fmaf(e, at[j], t);
        }
        #pragma unroll
        for (int o = 1; o < G; o <<= 1) t += __shfl_xor_sync(FULL, t, o);

        float p = __expf(fminf(t, 80.f));
        s += p;
        #pragma unroll
        for (int j = 0; j < CPL; j++) acc[j] = fmaf(p, a[j], acc[j]);

        ecur = enxt;
        xcur = xnxt;
    }

    float inv = 1.f / (s + 1e-16f);
    #pragma unroll
    for (int j = 0; j < CPL; j++) {
        float o = fmaf(acc[j], inv, bias[c0 + j]);
        if (DO_ELU) o = o > 0.f ? o : (__expf(o) - 1.f);
        out[(size_t)v * D + c0 + j] = o;
    }
}

// ---------------- launch ----------------
extern "C" void kernel_launch(void* const* d_in, const int* in_sizes, int n_in,
                              void* d_out, int out_size) {
    (void)in_sizes; (void)n_in; (void)out_size;
    const float* x    = (const float*)d_in[0];
    const int*   ei   = (const int*)  d_in[1];
    const float* ew   = (const float*)d_in[2];
    const float* Wl0  = (const float*)d_in[3];
    const float* bl0  = (const float*)d_in[4];
    const float* Wr0  = (const float*)d_in[5];
    const float* br0  = (const float*)d_in[6];
    const float* We0  = (const float*)d_in[7];
    const float* att0 = (const float*)d_in[8];
    const float* bias0= (const float*)d_in[9];
    const float* Wl1  = (const float*)d_in[10];
    const float* bl1  = (const float*)d_in[11];
    const float* Wr1  = (const float*)d_in[12];
    const float* br1  = (const float*)d_in[13];
    const float* We1  = (const float*)d_in[14];
    const float* att1 = (const float*)d_in[15];
    const float* bias1= (const float*)d_in[16];
    const float* Wl2  = (const float*)d_in[17];
    const float* bl2  = (const float*)d_in[18];
    const float* Wr2  = (const float*)d_in[19];
    const float* br2  = (const float*)d_in[20];
    const float* We2  = (const float*)d_in[21];
    const float* att2 = (const float*)d_in[22];
    const float* bias2= (const float*)d_in[23];
    float* out = (float*)d_out;

    __half *p_xl, *p_wimg; float *p_xr, *p_h;
    cudaGetSymbolAddress((void**)&p_xl,  g_xlh);
    cudaGetSymbolAddress((void**)&p_xr,  g_xr);
    cudaGetSymbolAddress((void**)&p_h,   g_h);
    cudaGetSymbolAddress((void**)&p_wimg, g_wimg);

    const int SM128 = (128 + 2 * 128) * 136 * 2;   // 104448 B
    const int SM64  = (128 + 2 * 64)  * 136 * 2;   //  69632 B
    cudaFuncSetAttribute(k_gemm_hmma<128>, cudaFuncAttributeMaxDynamicSharedMemorySize, SM128);
    cudaFuncSetAttribute(k_gemm_hmma<64>,  cudaFuncAttributeMaxDynamicSharedMemorySize, SM64);

    // CSR build + weight prep
    k_zero   <<<(NN + 255) / 256, 256>>>();
    k_hist   <<<(EE + 255) / 256, 256>>>(ei, ew);
    k_scan   <<<1, 1024>>>();
    k_scatter<<<(EE + 255) / 256, 256>>>(ei, ew);
    k_wprep  <<<(4 * 16384 + 2 * 8192 + 255) / 256, 256>>>(Wl0, Wr0, Wl1, Wr1, Wl2, Wr2);

    const int GEMM_GRID = (NN + 127) / 128;       // 391
    const int EDGE_GRID = (NN + 1) / 2;           // 2 warps / 64-thread block

    // layer 0: x -> g_h (ELU)
    k_gemm_hmma<128><<<GEMM_GRID, 256, SM128>>>(x, p_wimg, p_wimg + 16384,
                                                bl0, br0, p_xl, p_xr);
    k_edge<128, 4, true><<<EDGE_GRID, 64>>>(We0, att0, bias0, p_h);

    // layer 1: g_h -> g_h (ELU)
    k_gemm_hmma<128><<<GEMM_GRID, 256, SM128>>>(p_h, p_wimg + 32768, p_wimg + 49152,
                                                bl1, br1, p_xl, p_xr);
    k_edge<128, 4, true><<<EDGE_GRID, 64>>>(We1, att1, bias1, p_h);

    // layer 2: g_h -> out (no ELU, H=1, C=64)
    k_gemm_hmma<64><<<GEMM_GRID, 256, SM64>>>(p_h, p_wimg + 65536, p_wimg + 73728,
                                              bl2, br2, p_xl, p_xr);
    k_edge<64, 1, false><<<EDGE_GRID, 64>>>(We2, att2, bias2, out);
}